// round 4
// baseline (speedup 1.0000x reference)
#include <cuda_runtime.h>
#include <cuda_fp16.h>
#include <cstdint>

#define CDIV(a,b) (((a)+(b)-1)/(b))

// ---------------- static device scratch ----------------
__device__ __align__(16) half  g_WtpT [512 * 1024];
__device__ __align__(16) half  g_W2T  [512 * 64];
__device__ __align__(16) half  g_linWT[128 * 512];
__device__ __align__(16) float g_hidden[160000 * 64];
__device__ __align__(16) half  g_value [160000 * 512];
__device__ __align__(16) float g_alpha [250000 * 8];
__device__              int    g_seg   [160001];
__device__ __align__(16) half  g_fea   [160000 * 512];

// ---------------- mma helper ----------------
__device__ __forceinline__ void mma_f16(float* c, const uint32_t* a, const uint32_t* b) {
    asm volatile(
        "mma.sync.aligned.m16n8k16.row.col.f32.f16.f16.f32 "
        "{%0,%1,%2,%3},{%4,%5,%6,%7},{%8,%9},{%0,%1,%2,%3};\n"
        : "+f"(c[0]), "+f"(c[1]), "+f"(c[2]), "+f"(c[3])
        : "r"(a[0]), "r"(a[1]), "r"(a[2]), "r"(a[3]), "r"(b[0]), "r"(b[1]));
}

// one 64-deep K-chunk of mma on 128x128 tile; warp covers 32(m)x64(n)
__device__ __forceinline__ void tile_mma(const half* sA, const half* sB,
                                         int wm, int wn, int g, int tg,
                                         float acc[2][8][4]) {
#pragma unroll
    for (int ks = 0; ks < 4; ks++) {
        uint32_t af[2][4];
#pragma unroll
        for (int mt = 0; mt < 2; mt++) {
            const half* ap = sA + (wm + mt * 16 + g) * 72 + ks * 16 + tg * 2;
            af[mt][0] = *(const uint32_t*)ap;
            af[mt][1] = *(const uint32_t*)(ap + 8 * 72);
            af[mt][2] = *(const uint32_t*)(ap + 8);
            af[mt][3] = *(const uint32_t*)(ap + 8 * 72 + 8);
        }
#pragma unroll
        for (int nt = 0; nt < 8; nt++) {
            const half* bp = sB + (wn + nt * 8 + g) * 72 + ks * 16 + tg * 2;
            uint32_t bf[2] = { *(const uint32_t*)bp, *(const uint32_t*)(bp + 8) };
            mma_f16(acc[0][nt], af[0], bf);
            mma_f16(acc[1][nt], af[1], bf);
        }
    }
}

// copy 32 halfs (64 bytes) gmem->smem
__device__ __forceinline__ void cp32h(half* dst, const half* src) {
    uint4* d = (uint4*)dst;
    const uint4* s = (const uint4*)src;
    d[0] = s[0]; d[1] = s[1]; d[2] = s[2]; d[3] = s[3];
}

// ---------------- weight prep ----------------
__global__ void k_prep(const float* __restrict__ Wtp, const float* __restrict__ W2,
                       const float* __restrict__ linW) {
    int i = blockIdx.x * blockDim.x + threadIdx.x;
    int stride = gridDim.x * blockDim.x;
    for (int idx = i; idx < 512 * 1024; idx += stride) {
        int n = idx >> 10, k = idx & 1023;
        g_WtpT[idx] = __float2half_rn(Wtp[k * 512 + n]);
    }
    for (int idx = i; idx < 512 * 64; idx += stride) {
        int n = idx >> 6, k = idx & 63;
        g_W2T[idx] = __float2half_rn(W2[k * 512 + n]);
    }
    for (int idx = i; idx < 128 * 512; idx += stride) {
        int n = idx >> 9, k = idx & 511;
        g_linWT[idx] = __float2half_rn(linW[k * 128 + n]);
    }
}

// ---------------- hidden = silu(emb @ W1 + b1) ----------------
__global__ void k_hidden(const float* __restrict__ emb, const float* __restrict__ W1,
                         const float* __restrict__ b1, int E) {
    __shared__ float s_e[4][64];
    int tid = threadIdx.x;
    int slot = tid >> 6, j = tid & 63;
    int e = blockIdx.x * 4 + slot;
    int ec = min(e, E - 1);
    s_e[slot][j] = emb[ec * 64 + j];
    __syncthreads();
    float acc = b1[j];
#pragma unroll 8
    for (int i = 0; i < 64; i++) acc = fmaf(s_e[slot][i], W1[i * 64 + j], acc);
    float y = acc / (1.f + __expf(-acc));
    if (e < E) g_hidden[e * 64 + j] = y;
}

// ---------------- value = (z @ W_tp) * radial ----------------
__global__ __launch_bounds__(256) void k_value(const float* __restrict__ ein,
                                               const float* __restrict__ esh,
                                               const float* __restrict__ b2, int M) {
    __shared__ half sA[128 * 72];
    __shared__ half sB[128 * 72];
    int m0 = blockIdx.x * 128, n0 = blockIdx.y * 128;
    int tid = threadIdx.x, lane = tid & 31, wid = tid >> 5;
    int wm = (wid & 3) * 32, wn = (wid >> 2) * 64;
    int g = lane >> 2, tg = lane & 3;
    int row = tid >> 1, koff = (tid & 1) * 32;
    int erow = min(m0 + row, M - 1);

    float acc[2][8][4];
#pragma unroll
    for (int a = 0; a < 2; a++)
#pragma unroll
        for (int b = 0; b < 8; b++)
#pragma unroll
            for (int c = 0; c < 4; c++) acc[a][b][c] = 0.f;

    // ---- radial GEMM (K=64): A = hidden(fp32->fp16), B = W2T ----
    {
        const float* hp = g_hidden + erow * 64 + koff;
#pragma unroll
        for (int j = 0; j < 32; j += 2)
            *(half2*)&sA[row * 72 + koff + j] = __floats2half2_rn(hp[j], hp[j + 1]);
        cp32h(&sB[row * 72 + koff], g_W2T + (n0 + row) * 64 + koff);
    }
    __syncthreads();
    tile_mma(sA, sB, wm, wn, g, tg, acc);

    // stash radial (+bias) in fp32 regs, reset acc
    float rad[2][8][4];
#pragma unroll
    for (int mt = 0; mt < 2; mt++)
#pragma unroll
        for (int nt = 0; nt < 8; nt++) {
            int cn = n0 + wn + nt * 8 + tg * 2;
            float bb0 = b2[cn], bb1 = b2[cn + 1];
            rad[mt][nt][0] = acc[mt][nt][0] + bb0;
            rad[mt][nt][1] = acc[mt][nt][1] + bb1;
            rad[mt][nt][2] = acc[mt][nt][2] + bb0;
            rad[mt][nt][3] = acc[mt][nt][3] + bb1;
#pragma unroll
            for (int c = 0; c < 4; c++) acc[mt][nt][c] = 0.f;
        }

    // ---- main GEMM: K=1024 in 16 chunks, A built on the fly ----
    const float4* sp = (const float4*)(esh + erow * 16);
    float4 q0 = sp[0], q1 = sp[1], q2 = sp[2], q3 = sp[3];
    float shv[16] = {q0.x, q0.y, q0.z, q0.w, q1.x, q1.y, q1.z, q1.w,
                     q2.x, q2.y, q2.z, q2.w, q3.x, q3.y, q3.z, q3.w};
    for (int kc = 0; kc < 16; kc++) {
        __syncthreads();
        float c0v = ein[erow * 64 + kc * 4 + (koff >> 4)];
        float c1v = ein[erow * 64 + kc * 4 + (koff >> 4) + 1];
#pragma unroll
        for (int s = 0; s < 16; s += 2) {
            *(half2*)&sA[row * 72 + koff + s] = __floats2half2_rn(c0v * shv[s], c0v * shv[s + 1]);
            *(half2*)&sA[row * 72 + koff + 16 + s] = __floats2half2_rn(c1v * shv[s], c1v * shv[s + 1]);
        }
        cp32h(&sB[row * 72 + koff], g_WtpT + (n0 + row) * 1024 + kc * 64 + koff);
        __syncthreads();
        tile_mma(sA, sB, wm, wn, g, tg, acc);
    }

    // ---- epilogue: value = acc * radial, store fp16 ----
#pragma unroll
    for (int mt = 0; mt < 2; mt++)
#pragma unroll
        for (int nt = 0; nt < 8; nt++) {
            int er = m0 + wm + mt * 16 + g;
            int cn = n0 + wn + nt * 8 + tg * 2;
            if (er < M) {
                half2 v = __floats2half2_rn(acc[mt][nt][0] * rad[mt][nt][0],
                                            acc[mt][nt][1] * rad[mt][nt][1]);
                *(half2*)&g_value[er * 512 + cn] = v;
            }
            if (er + 8 < M) {
                half2 v = __floats2half2_rn(acc[mt][nt][2] * rad[mt][nt][2],
                                            acc[mt][nt][3] * rad[mt][nt][3]);
                *(half2*)&g_value[(er + 8) * 512 + cn] = v;
            }
        }
}

// ---------------- segment offsets (triple_idx0 sorted) ----------------
__global__ void k_seg(const int* __restrict__ t0, int E, int T) {
    int e = blockIdx.x * blockDim.x + threadIdx.x;
    if (e > E) return;
    int lo = 0, hi = T;
    while (lo < hi) {
        int mid = (lo + hi) >> 1;
        if (t0[mid] < e) lo = mid + 1; else hi = mid;
    }
    g_seg[e] = lo;
}

// ---------------- alpha MLPs (fp32, thread-per-triplet) ----------------
__global__ __launch_bounds__(96) void k_alpha(
    const float* __restrict__ emb2, const float* __restrict__ emb3,
    const float* __restrict__ aW1, const float* __restrict__ ab1,
    const float* __restrict__ ag1, const float* __restrict__ abe1,
    const float* __restrict__ aW2, const float* __restrict__ ab2,
    const float* __restrict__ ag2, const float* __restrict__ abe2,
    const float* __restrict__ aW3, const float* __restrict__ ab3, int T) {
    __shared__ float sW[64 * 64];
    __shared__ float sW3[64 * 8];
    __shared__ float sP[6 * 64];
    __shared__ float sb3[8];
    __shared__ float sx[64 * 97];
    int tid = threadIdx.x;
    int base = blockIdx.x * 96;
    int tri = base + tid;
    bool act = tri < T;
    float res[8];

    for (int br = 0; br < 2; br++) {
        const float* emb = br ? emb3 : emb2;
        __syncthreads();
        // x transpose load
        for (int li = tid; li < 96 * 64; li += 96) {
            int r = li >> 6, c = li & 63;
            int tt = min(base + r, T - 1);
            sx[c * 97 + r] = emb[tt * 64 + c];
        }
        for (int li = tid; li < 4096; li += 96) sW[li] = aW1[br * 4096 + li];
        for (int li = tid; li < 512; li += 96) sW3[li] = aW3[br * 512 + li];
        if (tid < 64) {
            sP[tid] = ab1[br * 64 + tid];       sP[64 + tid] = ag1[br * 64 + tid];
            sP[128 + tid] = abe1[br * 64 + tid]; sP[192 + tid] = ab2[br * 64 + tid];
            sP[256 + tid] = ag2[br * 64 + tid]; sP[320 + tid] = abe2[br * 64 + tid];
        }
        if (tid < 8) sb3[tid] = ab3[br * 8 + tid];
        __syncthreads();

        float h[64];
        // layer 1
#pragma unroll
        for (int j = 0; j < 64; j++) h[j] = sP[j];
        for (int i = 0; i < 64; i++) {
            float xv = sx[i * 97 + tid];
#pragma unroll
            for (int j = 0; j < 64; j++) h[j] = fmaf(xv, sW[i * 64 + j], h[j]);
        }
        {
            float mu = 0.f;
#pragma unroll
            for (int j = 0; j < 64; j++) mu += h[j];
            mu *= (1.f / 64.f);
            float v = 0.f;
#pragma unroll
            for (int j = 0; j < 64; j++) { float d = h[j] - mu; v = fmaf(d, d, v); }
            float r = rsqrtf(v * (1.f / 64.f) + 1e-6f);
#pragma unroll
            for (int j = 0; j < 64; j++) {
                float y = (h[j] - mu) * r * sP[64 + j] + sP[128 + j];
                sx[j * 97 + tid] = y / (1.f + __expf(-y));
            }
        }
        __syncthreads();
        for (int li = tid; li < 4096; li += 96) sW[li] = aW2[br * 4096 + li];
        __syncthreads();
        // layer 2
#pragma unroll
        for (int j = 0; j < 64; j++) h[j] = sP[192 + j];
        for (int i = 0; i < 64; i++) {
            float xv = sx[i * 97 + tid];
#pragma unroll
            for (int j = 0; j < 64; j++) h[j] = fmaf(xv, sW[i * 64 + j], h[j]);
        }
        {
            float mu = 0.f;
#pragma unroll
            for (int j = 0; j < 64; j++) mu += h[j];
            mu *= (1.f / 64.f);
            float v = 0.f;
#pragma unroll
            for (int j = 0; j < 64; j++) { float d = h[j] - mu; v = fmaf(d, d, v); }
            float r = rsqrtf(v * (1.f / 64.f) + 1e-6f);
#pragma unroll
            for (int j = 0; j < 64; j++) {
                float y = (h[j] - mu) * r * sP[256 + j] + sP[320 + j];
                sx[j * 97 + tid] = y / (1.f + __expf(-y));
            }
        }
        // layer 3 (reads own column only, no sync needed)
        float o[8];
#pragma unroll
        for (int j = 0; j < 8; j++) o[j] = sb3[j];
        for (int i = 0; i < 64; i++) {
            float xv = sx[i * 97 + tid];
#pragma unroll
            for (int j = 0; j < 8; j++) o[j] = fmaf(xv, sW3[i * 8 + j], o[j]);
        }
#pragma unroll
        for (int j = 0; j < 8; j++) res[j] = br ? res[j] * o[j] : o[j];
    }
    if (act) {
        float4* ap = (float4*)(g_alpha + tri * 8);
        ap[0] = make_float4(res[0], res[1], res[2], res[3]);
        ap[1] = make_float4(res[4], res[5], res[6], res[7]);
    }
}

// ---------------- segment softmax + gather-aggregate ----------------
__global__ void k_attn(const int* __restrict__ inv, const int* __restrict__ t1, int E) {
    int e = blockIdx.x * 8 + (threadIdx.x >> 5);
    if (e >= E) return;
    int lane = threadIdx.x & 31;
    int lo = g_seg[e], hi = g_seg[e + 1];
    int h = lane >> 2;
    float m = -1e30f;
    for (int t = lo; t < hi; t++) m = fmaxf(m, g_alpha[t * 8 + h]);
    float s = 0.f;
    for (int t = lo; t < hi; t++) s += __expf(g_alpha[t * 8 + h] - m);
    float inv_s = (s > 0.f) ? 1.f / s : 0.f;
    float acc[16];
#pragma unroll
    for (int j = 0; j < 16; j++) acc[j] = 0.f;
    for (int t = lo; t < hi; t++) {
        int es = inv[t1[t]];
        float w = __expf(g_alpha[t * 8 + h] - m) * inv_s;
        const uint4* vp = (const uint4*)(g_value + es * 512 + lane * 16);
        uint4 u0 = vp[0], u1 = vp[1];
        const half2* p0 = (const half2*)&u0;
        const half2* p1 = (const half2*)&u1;
#pragma unroll
        for (int j = 0; j < 4; j++) {
            float2 f0 = __half22float2(p0[j]);
            float2 f1 = __half22float2(p1[j]);
            acc[2 * j]     = fmaf(w, f0.x, acc[2 * j]);
            acc[2 * j + 1] = fmaf(w, f0.y, acc[2 * j + 1]);
            acc[8 + 2 * j]     = fmaf(w, f1.x, acc[8 + 2 * j]);
            acc[8 + 2 * j + 1] = fmaf(w, f1.y, acc[8 + 2 * j + 1]);
        }
    }
    half2 o[8];
#pragma unroll
    for (int j = 0; j < 8; j++) o[j] = __floats2half2_rn(acc[2 * j], acc[2 * j + 1]);
    uint4* fp = (uint4*)(g_fea + e * 512 + lane * 16);
    fp[0] = *(uint4*)&o[0];
    fp[1] = *(uint4*)&o[4];
}

// ---------------- out = fea @ lin_W + lin_b ----------------
__global__ __launch_bounds__(256) void k_out(const float* __restrict__ linb,
                                             float* __restrict__ out, int M) {
    __shared__ half sA[128 * 72];
    __shared__ half sB[128 * 72];
    int m0 = blockIdx.x * 128;
    int tid = threadIdx.x, lane = tid & 31, wid = tid >> 5;
    int wm = (wid & 3) * 32, wn = (wid >> 2) * 64;
    int g = lane >> 2, tg = lane & 3;
    int row = tid >> 1, koff = (tid & 1) * 32;
    int erow = min(m0 + row, M - 1);

    float acc[2][8][4];
#pragma unroll
    for (int a = 0; a < 2; a++)
#pragma unroll
        for (int b = 0; b < 8; b++)
#pragma unroll
            for (int c = 0; c < 4; c++) acc[a][b][c] = 0.f;

    for (int kc = 0; kc < 8; kc++) {
        __syncthreads();
        cp32h(&sA[row * 72 + koff], g_fea + erow * 512 + kc * 64 + koff);
        cp32h(&sB[row * 72 + koff], g_linWT + row * 512 + kc * 64 + koff);
        __syncthreads();
        tile_mma(sA, sB, wm, wn, g, tg, acc);
    }
#pragma unroll
    for (int mt = 0; mt < 2; mt++)
#pragma unroll
        for (int nt = 0; nt < 8; nt++) {
            int er = m0 + wm + mt * 16 + g;
            int cn = wn + nt * 8 + tg * 2;
            float bb0 = linb[cn], bb1 = linb[cn + 1];
            if (er < M) {
                float2 v = make_float2(acc[mt][nt][0] + bb0, acc[mt][nt][1] + bb1);
                *(float2*)&out[er * 128 + cn] = v;
            }
            if (er + 8 < M) {
                float2 v = make_float2(acc[mt][nt][2] + bb0, acc[mt][nt][3] + bb1);
                *(float2*)&out[(er + 8) * 128 + cn] = v;
            }
        }
}

// ---------------- launcher ----------------
extern "C" void kernel_launch(void* const* d_in, const int* in_sizes, int n_in,
                              void* d_out, int out_size) {
    const float* edge_in = (const float*)d_in[0];
    const int*   inv     = (const int*)d_in[1];
    const float* esh     = (const float*)d_in[2];
    const float* elen    = (const float*)d_in[3];
    const int*   t0      = (const int*)d_in[6];
    const int*   t1      = (const int*)d_in[7];
    const float* emb2    = (const float*)d_in[8];
    const float* emb3    = (const float*)d_in[9];
    const float* Wtp     = (const float*)d_in[11];
    const float* rW1     = (const float*)d_in[12];
    const float* rb1     = (const float*)d_in[13];
    const float* rW2     = (const float*)d_in[14];
    const float* rb2     = (const float*)d_in[15];
    const float* aW1     = (const float*)d_in[16];
    const float* ab1     = (const float*)d_in[17];
    const float* ag1     = (const float*)d_in[18];
    const float* abe1    = (const float*)d_in[19];
    const float* aW2     = (const float*)d_in[20];
    const float* ab2     = (const float*)d_in[21];
    const float* ag2     = (const float*)d_in[22];
    const float* abe2    = (const float*)d_in[23];
    const float* aW3     = (const float*)d_in[24];
    const float* ab3     = (const float*)d_in[25];
    const float* linW    = (const float*)d_in[26];
    const float* linb    = (const float*)d_in[27];
    int E = in_sizes[0] / 64;
    int T = in_sizes[6];

    k_prep<<<256, 256>>>(Wtp, rW2, linW);
    k_hidden<<<CDIV(E, 4), 256>>>(elen, rW1, rb1, E);
    k_value<<<dim3(CDIV(E, 128), 4), 256>>>(edge_in, esh, rb2, E);
    k_seg<<<CDIV(E + 1, 256), 256>>>(t0, E, T);
    k_alpha<<<CDIV(T, 96), 96>>>(emb2, emb3, aW1, ab1, ag1, abe1,
                                 aW2, ab2, ag2, abe2, aW3, ab3, T);
    k_attn<<<CDIV(E, 8), 256>>>(inv, t1, E);
    k_out<<<CDIV(E, 128), 256>>>(linb, (float*)d_out, E);
}

// round 5
// speedup vs baseline: 1.1225x; 1.1225x over previous
#include <cuda_runtime.h>
#include <cuda_fp16.h>
#include <cstdint>

#define CDIV(a,b) (((a)+(b)-1)/(b))

// ---------------- static device scratch ----------------
__device__ __align__(16) half  g_WtpT  [512 * 1024];
__device__ __align__(16) half  g_W2T   [512 * 64];
__device__ __align__(16) half  g_linWT [128 * 512];
__device__ __align__(16) float g_hidden[160000 * 64];
__device__ __align__(16) half  g_radial[160000 * 512];
__device__ __align__(16) half  g_value [160000 * 512];
__device__ __align__(16) float g_alpha [250000 * 8];
__device__              int    g_seg   [160001];
__device__ __align__(16) half  g_fea   [160000 * 512];

// ---------------- PTX helpers ----------------
__device__ __forceinline__ void mma_f16(float* c, const uint32_t* a, const uint32_t* b) {
    asm volatile(
        "mma.sync.aligned.m16n8k16.row.col.f32.f16.f16.f32 "
        "{%0,%1,%2,%3},{%4,%5,%6,%7},{%8,%9},{%0,%1,%2,%3};\n"
        : "+f"(c[0]), "+f"(c[1]), "+f"(c[2]), "+f"(c[3])
        : "r"(a[0]), "r"(a[1]), "r"(a[2]), "r"(a[3]), "r"(b[0]), "r"(b[1]));
}

__device__ __forceinline__ void ldsm4(uint32_t* d, const half* p) {
    uint32_t a = (uint32_t)__cvta_generic_to_shared(p);
    asm volatile("ldmatrix.sync.aligned.m8n8.x4.shared.b16 {%0,%1,%2,%3},[%4];\n"
        : "=r"(d[0]), "=r"(d[1]), "=r"(d[2]), "=r"(d[3]) : "r"(a));
}

__device__ __forceinline__ void cp16(half* smem, const half* gmem) {
    uint32_t s = (uint32_t)__cvta_generic_to_shared(smem);
    asm volatile("cp.async.cg.shared.global [%0], [%1], 16;\n" :: "r"(s), "l"(gmem));
}
#define CP_COMMIT() asm volatile("cp.async.commit_group;\n")
#define CP_WAIT0()  asm volatile("cp.async.wait_group 0;\n")

// one 64-deep K-chunk of mma on 128x128 tile; warp covers 32(m)x64(n).
// smem row stride = 72 halfs (144B): ldmatrix row addrs hit 32 distinct banks.
__device__ __forceinline__ void tile_mma(const half* sA, const half* sB,
                                         int wm, int wn, int lane,
                                         float acc[2][8][4]) {
    int r15 = lane & 15;
    int a_k8 = ((lane >> 4) & 1) * 8;
    int b_r8 = ((lane >> 4) & 1) * 8;
    int b_k8 = lane & 8;
    int l7 = lane & 7;
#pragma unroll
    for (int ks = 0; ks < 4; ks++) {
        uint32_t af[2][4];
#pragma unroll
        for (int mt = 0; mt < 2; mt++)
            ldsm4(af[mt], sA + (wm + mt * 16 + r15) * 72 + ks * 16 + a_k8);
        uint32_t bf[4][4];
#pragma unroll
        for (int np = 0; np < 4; np++)
            ldsm4(bf[np], sB + (wn + np * 16 + b_r8 + l7) * 72 + ks * 16 + b_k8);
#pragma unroll
        for (int np = 0; np < 4; np++) {
            mma_f16(acc[0][2 * np],     af[0], &bf[np][0]);
            mma_f16(acc[0][2 * np + 1], af[0], &bf[np][2]);
            mma_f16(acc[1][2 * np],     af[1], &bf[np][0]);
            mma_f16(acc[1][2 * np + 1], af[1], &bf[np][2]);
        }
    }
}

// ---------------- weight prep ----------------
__global__ void k_prep(const float* __restrict__ Wtp, const float* __restrict__ W2,
                       const float* __restrict__ linW) {
    int i = blockIdx.x * blockDim.x + threadIdx.x;
    int stride = gridDim.x * blockDim.x;
    for (int idx = i; idx < 512 * 1024; idx += stride) {
        int n = idx >> 10, k = idx & 1023;
        g_WtpT[idx] = __float2half_rn(Wtp[k * 512 + n]);
    }
    for (int idx = i; idx < 512 * 64; idx += stride) {
        int n = idx >> 6, k = idx & 63;
        g_W2T[idx] = __float2half_rn(W2[k * 512 + n]);
    }
    for (int idx = i; idx < 128 * 512; idx += stride) {
        int n = idx >> 9, k = idx & 511;
        g_linWT[idx] = __float2half_rn(linW[k * 128 + n]);
    }
}

// ---------------- hidden = silu(emb @ W1 + b1) ----------------
__global__ void k_hidden(const float* __restrict__ emb, const float* __restrict__ W1,
                         const float* __restrict__ b1, int E) {
    __shared__ float s_e[4][64];
    int tid = threadIdx.x;
    int slot = tid >> 6, j = tid & 63;
    int e = blockIdx.x * 4 + slot;
    int ec = min(e, E - 1);
    s_e[slot][j] = emb[ec * 64 + j];
    __syncthreads();
    float acc = b1[j];
#pragma unroll 8
    for (int i = 0; i < 64; i++) acc = fmaf(s_e[slot][i], W1[i * 64 + j], acc);
    float y = acc / (1.f + __expf(-acc));
    if (e < E) g_hidden[e * 64 + j] = y;
}

// ---------------- radial = hidden @ W2 + b2  (K=64 mma) ----------------
__global__ __launch_bounds__(256) void k_radial(const float* __restrict__ b2, int M) {
    __shared__ half sA[128 * 72];
    __shared__ half sB[128 * 72];
    int m0 = blockIdx.x * 128, n0 = blockIdx.y * 128;
    int tid = threadIdx.x, lane = tid & 31, wid = tid >> 5;
    int wm = (wid & 3) * 32, wn = (wid >> 2) * 64;
    int g = lane >> 2, tg = lane & 3;
    int row = tid >> 1, koff = (tid & 1) * 32;
    int erow = min(m0 + row, M - 1);

    float acc[2][8][4];
#pragma unroll
    for (int a = 0; a < 2; a++)
#pragma unroll
        for (int b = 0; b < 8; b++)
#pragma unroll
            for (int c = 0; c < 4; c++) acc[a][b][c] = 0.f;

    const float4* hp = (const float4*)(g_hidden + erow * 64 + koff);
#pragma unroll
    for (int j = 0; j < 8; j++) {
        float4 v = hp[j];
        *(half2*)&sA[row * 72 + koff + j * 4]     = __floats2half2_rn(v.x, v.y);
        *(half2*)&sA[row * 72 + koff + j * 4 + 2] = __floats2half2_rn(v.z, v.w);
    }
    {
        const uint4* s = (const uint4*)(g_W2T + (n0 + row) * 64 + koff);
        uint4* d = (uint4*)&sB[row * 72 + koff];
        d[0] = s[0]; d[1] = s[1]; d[2] = s[2]; d[3] = s[3];
    }
    __syncthreads();
    tile_mma(sA, sB, wm, wn, lane, acc);

#pragma unroll
    for (int mt = 0; mt < 2; mt++)
#pragma unroll
        for (int nt = 0; nt < 8; nt++) {
            int er = m0 + wm + mt * 16 + g;
            int cn = n0 + wn + nt * 8 + tg * 2;
            float bb0 = b2[cn], bb1 = b2[cn + 1];
            if (er < M)
                *(half2*)&g_radial[er * 512 + cn] =
                    __floats2half2_rn(acc[mt][nt][0] + bb0, acc[mt][nt][1] + bb1);
            if (er + 8 < M)
                *(half2*)&g_radial[(er + 8) * 512 + cn] =
                    __floats2half2_rn(acc[mt][nt][2] + bb0, acc[mt][nt][3] + bb1);
        }
}

// ---------------- value = (z @ W_tp) * radial  (K=1024, pipelined) ----------------
__device__ __forceinline__ void build_A(half* sA, const float* __restrict__ ein,
                                        int erow, int row, int koff,
                                        const float* shv, int kc) {
    float c0v = __ldg(&ein[erow * 64 + kc * 4 + (koff >> 4)]);
    float c1v = __ldg(&ein[erow * 64 + kc * 4 + (koff >> 4) + 1]);
#pragma unroll
    for (int s = 0; s < 16; s += 2) {
        *(half2*)&sA[row * 72 + koff + s]      = __floats2half2_rn(c0v * shv[s], c0v * shv[s + 1]);
        *(half2*)&sA[row * 72 + koff + 16 + s] = __floats2half2_rn(c1v * shv[s], c1v * shv[s + 1]);
    }
}

__device__ __forceinline__ void load_B(half* sB, int n0, int row, int koff, int kc) {
    const half* src = g_WtpT + (n0 + row) * 1024 + kc * 64 + koff;
    half* dst = &sB[row * 72 + koff];
#pragma unroll
    for (int j = 0; j < 4; j++) cp16(dst + j * 8, src + j * 8);
}

__global__ __launch_bounds__(256, 2) void k_value(const float* __restrict__ ein,
                                                  const float* __restrict__ esh, int M) {
    __shared__ half sA[2][128 * 72];
    __shared__ half sB[2][128 * 72];
    int m0 = blockIdx.x * 128, n0 = blockIdx.y * 128;
    int tid = threadIdx.x, lane = tid & 31, wid = tid >> 5;
    int wm = (wid & 3) * 32, wn = (wid >> 2) * 64;
    int g = lane >> 2, tg = lane & 3;
    int row = tid >> 1, koff = (tid & 1) * 32;
    int erow = min(m0 + row, M - 1);

    float acc[2][8][4];
#pragma unroll
    for (int a = 0; a < 2; a++)
#pragma unroll
        for (int b = 0; b < 8; b++)
#pragma unroll
            for (int c = 0; c < 4; c++) acc[a][b][c] = 0.f;

    const float4* sp = (const float4*)(esh + erow * 16);
    float4 q0 = sp[0], q1 = sp[1], q2 = sp[2], q3 = sp[3];
    float shv[16] = {q0.x, q0.y, q0.z, q0.w, q1.x, q1.y, q1.z, q1.w,
                     q2.x, q2.y, q2.z, q2.w, q3.x, q3.y, q3.z, q3.w};

    // prologue: stage chunk 0
    load_B(sB[0], n0, row, koff, 0);
    CP_COMMIT();
    build_A(sA[0], ein, erow, row, koff, shv, 0);
    CP_WAIT0();
    __syncthreads();

    for (int kc = 0; kc < 16; kc++) {
        int p = kc & 1;
        if (kc < 15) { load_B(sB[1 - p], n0, row, koff, kc + 1); CP_COMMIT(); }
        tile_mma(sA[p], sB[p], wm, wn, lane, acc);
        if (kc < 15) {
            build_A(sA[1 - p], ein, erow, row, koff, shv, kc + 1);
            CP_WAIT0();
            __syncthreads();
        }
    }

    // epilogue: value = acc * radial (radial fp16, incl. bias)
#pragma unroll
    for (int mt = 0; mt < 2; mt++)
#pragma unroll
        for (int nt = 0; nt < 8; nt++) {
            int er = m0 + wm + mt * 16 + g;
            int cn = n0 + wn + nt * 8 + tg * 2;
            if (er < M) {
                float2 r = __half22float2(*(const half2*)&g_radial[er * 512 + cn]);
                *(half2*)&g_value[er * 512 + cn] =
                    __floats2half2_rn(acc[mt][nt][0] * r.x, acc[mt][nt][1] * r.y);
            }
            if (er + 8 < M) {
                float2 r = __half22float2(*(const half2*)&g_radial[(er + 8) * 512 + cn]);
                *(half2*)&g_value[(er + 8) * 512 + cn] =
                    __floats2half2_rn(acc[mt][nt][2] * r.x, acc[mt][nt][3] * r.y);
            }
        }
}

// ---------------- segment offsets (triple_idx0 sorted) ----------------
__global__ void k_seg(const int* __restrict__ t0, int E, int T) {
    int e = blockIdx.x * blockDim.x + threadIdx.x;
    if (e > E) return;
    int lo = 0, hi = T;
    while (lo < hi) {
        int mid = (lo + hi) >> 1;
        if (t0[mid] < e) lo = mid + 1; else hi = mid;
    }
    g_seg[e] = lo;
}

// ---------------- alpha MLPs (fp32, thread-per-triplet) ----------------
__global__ __launch_bounds__(128) void k_alpha(
    const float* __restrict__ emb2, const float* __restrict__ emb3,
    const float* __restrict__ aW1, const float* __restrict__ ab1,
    const float* __restrict__ ag1, const float* __restrict__ abe1,
    const float* __restrict__ aW2, const float* __restrict__ ab2,
    const float* __restrict__ ag2, const float* __restrict__ abe2,
    const float* __restrict__ aW3, const float* __restrict__ ab3, int T) {
    __shared__ float sW[64 * 64];
    __shared__ float sW3[64 * 8];
    __shared__ float sP[6 * 64];
    __shared__ float sb3[8];
    __shared__ float sx[64 * 129];
    int tid = threadIdx.x;
    int base = blockIdx.x * 128;
    int tri = base + tid;
    bool act = tri < T;
    float res[8];

    for (int br = 0; br < 2; br++) {
        const float* emb = br ? emb3 : emb2;
        __syncthreads();
        for (int li = tid; li < 128 * 64; li += 128) {
            int r = li >> 6, c = li & 63;
            int tt = min(base + r, T - 1);
            sx[c * 129 + r] = emb[tt * 64 + c];
        }
        for (int li = tid; li < 4096; li += 128) sW[li] = aW1[br * 4096 + li];
        for (int li = tid; li < 512; li += 128) sW3[li] = aW3[br * 512 + li];
        if (tid < 64) {
            sP[tid] = ab1[br * 64 + tid];        sP[64 + tid] = ag1[br * 64 + tid];
            sP[128 + tid] = abe1[br * 64 + tid]; sP[192 + tid] = ab2[br * 64 + tid];
            sP[256 + tid] = ag2[br * 64 + tid];  sP[320 + tid] = abe2[br * 64 + tid];
        }
        if (tid < 8) sb3[tid] = ab3[br * 8 + tid];
        __syncthreads();

        const float4* sW4 = (const float4*)sW;
        float h[64];
        // layer 1
#pragma unroll
        for (int j = 0; j < 64; j++) h[j] = sP[j];
        for (int i = 0; i < 64; i++) {
            float xv = sx[i * 129 + tid];
#pragma unroll
            for (int j4 = 0; j4 < 16; j4++) {
                float4 w = sW4[i * 16 + j4];
                h[4 * j4]     = fmaf(xv, w.x, h[4 * j4]);
                h[4 * j4 + 1] = fmaf(xv, w.y, h[4 * j4 + 1]);
                h[4 * j4 + 2] = fmaf(xv, w.z, h[4 * j4 + 2]);
                h[4 * j4 + 3] = fmaf(xv, w.w, h[4 * j4 + 3]);
            }
        }
        {
            float mu = 0.f;
#pragma unroll
            for (int j = 0; j < 64; j++) mu += h[j];
            mu *= (1.f / 64.f);
            float v = 0.f;
#pragma unroll
            for (int j = 0; j < 64; j++) { float d = h[j] - mu; v = fmaf(d, d, v); }
            float r = rsqrtf(v * (1.f / 64.f) + 1e-6f);
#pragma unroll
            for (int j = 0; j < 64; j++) {
                float y = (h[j] - mu) * r * sP[64 + j] + sP[128 + j];
                sx[j * 129 + tid] = y / (1.f + __expf(-y));
            }
        }
        __syncthreads();
        for (int li = tid; li < 4096; li += 128) sW[li] = aW2[br * 4096 + li];
        __syncthreads();
        // layer 2
#pragma unroll
        for (int j = 0; j < 64; j++) h[j] = sP[192 + j];
        for (int i = 0; i < 64; i++) {
            float xv = sx[i * 129 + tid];
#pragma unroll
            for (int j4 = 0; j4 < 16; j4++) {
                float4 w = sW4[i * 16 + j4];
                h[4 * j4]     = fmaf(xv, w.x, h[4 * j4]);
                h[4 * j4 + 1] = fmaf(xv, w.y, h[4 * j4 + 1]);
                h[4 * j4 + 2] = fmaf(xv, w.z, h[4 * j4 + 2]);
                h[4 * j4 + 3] = fmaf(xv, w.w, h[4 * j4 + 3]);
            }
        }
        {
            float mu = 0.f;
#pragma unroll
            for (int j = 0; j < 64; j++) mu += h[j];
            mu *= (1.f / 64.f);
            float v = 0.f;
#pragma unroll
            for (int j = 0; j < 64; j++) { float d = h[j] - mu; v = fmaf(d, d, v); }
            float r = rsqrtf(v * (1.f / 64.f) + 1e-6f);
#pragma unroll
            for (int j = 0; j < 64; j++) {
                float y = (h[j] - mu) * r * sP[256 + j] + sP[320 + j];
                sx[j * 129 + tid] = y / (1.f + __expf(-y));
            }
        }
        // layer 3 (reads own column only)
        const float4* sW34 = (const float4*)sW3;
        float o[8];
#pragma unroll
        for (int j = 0; j < 8; j++) o[j] = sb3[j];
        for (int i = 0; i < 64; i++) {
            float xv = sx[i * 129 + tid];
            float4 w0 = sW34[i * 2], w1 = sW34[i * 2 + 1];
            o[0] = fmaf(xv, w0.x, o[0]); o[1] = fmaf(xv, w0.y, o[1]);
            o[2] = fmaf(xv, w0.z, o[2]); o[3] = fmaf(xv, w0.w, o[3]);
            o[4] = fmaf(xv, w1.x, o[4]); o[5] = fmaf(xv, w1.y, o[5]);
            o[6] = fmaf(xv, w1.z, o[6]); o[7] = fmaf(xv, w1.w, o[7]);
        }
#pragma unroll
        for (int j = 0; j < 8; j++) res[j] = br ? res[j] * o[j] : o[j];
    }
    if (act) {
        float4* ap = (float4*)(g_alpha + tri * 8);
        ap[0] = make_float4(res[0], res[1], res[2], res[3]);
        ap[1] = make_float4(res[4], res[5], res[6], res[7]);
    }
}

// ---------------- segment softmax + gather-aggregate ----------------
__global__ void k_attn(const int* __restrict__ inv, const int* __restrict__ t1, int E) {
    int e = blockIdx.x * 8 + (threadIdx.x >> 5);
    if (e >= E) return;
    int lane = threadIdx.x & 31;
    int lo = g_seg[e], hi = g_seg[e + 1];
    int h = lane >> 2;
    float m = -1e30f;
    for (int t = lo; t < hi; t++) m = fmaxf(m, g_alpha[t * 8 + h]);
    float s = 0.f;
    for (int t = lo; t < hi; t++) s += __expf(g_alpha[t * 8 + h] - m);
    float inv_s = (s > 0.f) ? 1.f / s : 0.f;
    float acc[16];
#pragma unroll
    for (int j = 0; j < 16; j++) acc[j] = 0.f;
    for (int t = lo; t < hi; t++) {
        int es = inv[t1[t]];
        float w = __expf(g_alpha[t * 8 + h] - m) * inv_s;
        const uint4* vp = (const uint4*)(g_value + es * 512 + lane * 16);
        uint4 u0 = vp[0], u1 = vp[1];
        const half2* p0 = (const half2*)&u0;
        const half2* p1 = (const half2*)&u1;
#pragma unroll
        for (int j = 0; j < 4; j++) {
            float2 f0 = __half22float2(p0[j]);
            float2 f1 = __half22float2(p1[j]);
            acc[2 * j]         = fmaf(w, f0.x, acc[2 * j]);
            acc[2 * j + 1]     = fmaf(w, f0.y, acc[2 * j + 1]);
            acc[8 + 2 * j]     = fmaf(w, f1.x, acc[8 + 2 * j]);
            acc[8 + 2 * j + 1] = fmaf(w, f1.y, acc[8 + 2 * j + 1]);
        }
    }
    half2 o[8];
#pragma unroll
    for (int j = 0; j < 8; j++) o[j] = __floats2half2_rn(acc[2 * j], acc[2 * j + 1]);
    uint4* fp = (uint4*)(g_fea + e * 512 + lane * 16);
    fp[0] = *(uint4*)&o[0];
    fp[1] = *(uint4*)&o[4];
}

// ---------------- out = fea @ lin_W + lin_b ----------------
__global__ __launch_bounds__(256) void k_out(const float* __restrict__ linb,
                                             float* __restrict__ out, int M) {
    __shared__ half sA[128 * 72];
    __shared__ half sB[128 * 72];
    int m0 = blockIdx.x * 128;
    int tid = threadIdx.x, lane = tid & 31, wid = tid >> 5;
    int wm = (wid & 3) * 32, wn = (wid >> 2) * 64;
    int g = lane >> 2, tg = lane & 3;
    int row = tid >> 1, koff = (tid & 1) * 32;
    int erow = min(m0 + row, M - 1);

    float acc[2][8][4];
#pragma unroll
    for (int a = 0; a < 2; a++)
#pragma unroll
        for (int b = 0; b < 8; b++)
#pragma unroll
            for (int c = 0; c < 4; c++) acc[a][b][c] = 0.f;

    for (int kc = 0; kc < 8; kc++) {
        __syncthreads();
        {
            const uint4* s = (const uint4*)(g_fea + erow * 512 + kc * 64 + koff);
            uint4* d = (uint4*)&sA[row * 72 + koff];
            d[0] = s[0]; d[1] = s[1]; d[2] = s[2]; d[3] = s[3];
            const uint4* s2 = (const uint4*)(g_linWT + row * 512 + kc * 64 + koff);
            uint4* d2 = (uint4*)&sB[row * 72 + koff];
            d2[0] = s2[0]; d2[1] = s2[1]; d2[2] = s2[2]; d2[3] = s2[3];
        }
        __syncthreads();
        tile_mma(sA, sB, wm, wn, lane, acc);
    }
#pragma unroll
    for (int mt = 0; mt < 2; mt++)
#pragma unroll
        for (int nt = 0; nt < 8; nt++) {
            int er = m0 + wm + mt * 16 + g;
            int cn = wn + nt * 8 + tg * 2;
            float bb0 = linb[cn], bb1 = linb[cn + 1];
            if (er < M)
                *(float2*)&out[er * 128 + cn] =
                    make_float2(acc[mt][nt][0] + bb0, acc[mt][nt][1] + bb1);
            if (er + 8 < M)
                *(float2*)&out[(er + 8) * 128 + cn] =
                    make_float2(acc[mt][nt][2] + bb0, acc[mt][nt][3] + bb1);
        }
}

// ---------------- launcher ----------------
extern "C" void kernel_launch(void* const* d_in, const int* in_sizes, int n_in,
                              void* d_out, int out_size) {
    const float* edge_in = (const float*)d_in[0];
    const int*   inv     = (const int*)d_in[1];
    const float* esh     = (const float*)d_in[2];
    const float* elen    = (const float*)d_in[3];
    const int*   t0      = (const int*)d_in[6];
    const int*   t1      = (const int*)d_in[7];
    const float* emb2    = (const float*)d_in[8];
    const float* emb3    = (const float*)d_in[9];
    const float* Wtp     = (const float*)d_in[11];
    const float* rW1     = (const float*)d_in[12];
    const float* rb1     = (const float*)d_in[13];
    const float* rW2     = (const float*)d_in[14];
    const float* rb2     = (const float*)d_in[15];
    const float* aW1     = (const float*)d_in[16];
    const float* ab1     = (const float*)d_in[17];
    const float* ag1     = (const float*)d_in[18];
    const float* abe1    = (const float*)d_in[19];
    const float* aW2     = (const float*)d_in[20];
    const float* ab2     = (const float*)d_in[21];
    const float* ag2     = (const float*)d_in[22];
    const float* abe2    = (const float*)d_in[23];
    const float* aW3     = (const float*)d_in[24];
    const float* ab3     = (const float*)d_in[25];
    const float* linW    = (const float*)d_in[26];
    const float* linb    = (const float*)d_in[27];
    int E = in_sizes[0] / 64;
    int T = in_sizes[6];

    k_prep<<<512, 256>>>(Wtp, rW2, linW);
    k_hidden<<<CDIV(E, 4), 256>>>(elen, rW1, rb1, E);
    k_radial<<<dim3(CDIV(E, 128), 4), 256>>>(rb2, E);
    k_value<<<dim3(CDIV(E, 128), 4), 256>>>(edge_in, esh, E);
    k_seg<<<CDIV(E + 1, 256), 256>>>(t0, E, T);
    k_alpha<<<CDIV(T, 128), 128>>>(emb2, emb3, aW1, ab1, ag1, abe1,
                                   aW2, ab2, ag2, abe2, aW3, ab3, T);
    k_attn<<<CDIV(E, 8), 256>>>(inv, t1, E);
    k_out<<<CDIV(E, 128), 256>>>(linb, (float*)d_out, E);
}

// round 6
// speedup vs baseline: 1.1865x; 1.0570x over previous
#include <cuda_runtime.h>
#include <cuda_fp16.h>
#include <cstdint>

#define CDIV(a,b) (((a)+(b)-1)/(b))

// ---------------- static device scratch ----------------
__device__ __align__(16) half  g_WtpT  [512 * 1024];
__device__ __align__(16) half  g_W2T   [512 * 64];
__device__ __align__(16) half  g_linWT [128 * 512];
__device__ __align__(16) float g_hidden[160000 * 64];
__device__ __align__(16) half  g_radial[160000 * 512];
__device__ __align__(16) half  g_value [160000 * 512];
__device__ __align__(16) float g_alpha [250000 * 8];
__device__              int    g_seg   [160001];
__device__ __align__(16) half  g_fea   [160000 * 512];

// ---------------- PTX helpers ----------------
__device__ __forceinline__ void mma_f16(float* c, const uint32_t* a, const uint32_t* b) {
    asm volatile(
        "mma.sync.aligned.m16n8k16.row.col.f32.f16.f16.f32 "
        "{%0,%1,%2,%3},{%4,%5,%6,%7},{%8,%9},{%0,%1,%2,%3};\n"
        : "+f"(c[0]), "+f"(c[1]), "+f"(c[2]), "+f"(c[3])
        : "r"(a[0]), "r"(a[1]), "r"(a[2]), "r"(a[3]), "r"(b[0]), "r"(b[1]));
}

__device__ __forceinline__ void ldsm4(uint32_t* d, const half* p) {
    uint32_t a = (uint32_t)__cvta_generic_to_shared(p);
    asm volatile("ldmatrix.sync.aligned.m8n8.x4.shared.b16 {%0,%1,%2,%3},[%4];\n"
        : "=r"(d[0]), "=r"(d[1]), "=r"(d[2]), "=r"(d[3]) : "r"(a));
}

__device__ __forceinline__ void cp16(half* smem, const half* gmem) {
    uint32_t s = (uint32_t)__cvta_generic_to_shared(smem);
    asm volatile("cp.async.cg.shared.global [%0], [%1], 16;\n" :: "r"(s), "l"(gmem));
}
#define CP_COMMIT() asm volatile("cp.async.commit_group;\n")
#define CP_WAIT0()  asm volatile("cp.async.wait_group 0;\n")

__device__ __forceinline__ uint32_t packh2(float a, float b) {
    half2 h = __floats2half2_rn(a, b);
    return *(uint32_t*)&h;
}

// one 64-deep K-chunk of mma on 128x128 tile; warp covers 32(m)x64(n).
// smem row stride = 72 halfs (144B): ldmatrix row addrs hit 32 distinct banks.
__device__ __forceinline__ void tile_mma(const half* sA, const half* sB,
                                         int wm, int wn, int lane,
                                         float acc[2][8][4]) {
    int r15 = lane & 15;
    int a_k8 = ((lane >> 4) & 1) * 8;
    int b_r8 = ((lane >> 4) & 1) * 8;
    int b_k8 = lane & 8;
    int l7 = lane & 7;
#pragma unroll
    for (int ks = 0; ks < 4; ks++) {
        uint32_t af[2][4];
#pragma unroll
        for (int mt = 0; mt < 2; mt++)
            ldsm4(af[mt], sA + (wm + mt * 16 + r15) * 72 + ks * 16 + a_k8);
        uint32_t bf[4][4];
#pragma unroll
        for (int np = 0; np < 4; np++)
            ldsm4(bf[np], sB + (wn + np * 16 + b_r8 + l7) * 72 + ks * 16 + b_k8);
#pragma unroll
        for (int np = 0; np < 4; np++) {
            mma_f16(acc[0][2 * np],     af[0], &bf[np][0]);
            mma_f16(acc[0][2 * np + 1], af[0], &bf[np][2]);
            mma_f16(acc[1][2 * np],     af[1], &bf[np][0]);
            mma_f16(acc[1][2 * np + 1], af[1], &bf[np][2]);
        }
    }
}

// ---------------- weight prep ----------------
__global__ void k_prep(const float* __restrict__ Wtp, const float* __restrict__ W2,
                       const float* __restrict__ linW) {
    int i = blockIdx.x * blockDim.x + threadIdx.x;
    int stride = gridDim.x * blockDim.x;
    for (int idx = i; idx < 512 * 1024; idx += stride) {
        int n = idx >> 10, k = idx & 1023;
        g_WtpT[idx] = __float2half_rn(Wtp[k * 512 + n]);
    }
    for (int idx = i; idx < 512 * 64; idx += stride) {
        int n = idx >> 6, k = idx & 63;
        g_W2T[idx] = __float2half_rn(W2[k * 512 + n]);
    }
    for (int idx = i; idx < 128 * 512; idx += stride) {
        int n = idx >> 9, k = idx & 511;
        g_linWT[idx] = __float2half_rn(linW[k * 128 + n]);
    }
}

// ---------------- hidden = silu(emb @ W1 + b1) ----------------
__global__ void k_hidden(const float* __restrict__ emb, const float* __restrict__ W1,
                         const float* __restrict__ b1, int E) {
    __shared__ float s_e[4][64];
    int tid = threadIdx.x;
    int slot = tid >> 6, j = tid & 63;
    int e = blockIdx.x * 4 + slot;
    int ec = min(e, E - 1);
    s_e[slot][j] = emb[ec * 64 + j];
    __syncthreads();
    float acc = b1[j];
#pragma unroll 8
    for (int i = 0; i < 64; i++) acc = fmaf(s_e[slot][i], W1[i * 64 + j], acc);
    float y = acc / (1.f + __expf(-acc));
    if (e < E) g_hidden[e * 64 + j] = y;
}

// ---------------- radial = hidden @ W2 + b2  (K=64 mma) ----------------
__global__ __launch_bounds__(256) void k_radial(const float* __restrict__ b2, int M) {
    __shared__ half sA[128 * 72];
    __shared__ half sB[128 * 72];
    int m0 = blockIdx.x * 128, n0 = blockIdx.y * 128;
    int tid = threadIdx.x, lane = tid & 31, wid = tid >> 5;
    int wm = (wid & 3) * 32, wn = (wid >> 2) * 64;
    int g = lane >> 2, tg = lane & 3;
    int row = tid >> 1, koff = (tid & 1) * 32;
    int erow = min(m0 + row, M - 1);

    float acc[2][8][4];
#pragma unroll
    for (int a = 0; a < 2; a++)
#pragma unroll
        for (int b = 0; b < 8; b++)
#pragma unroll
            for (int c = 0; c < 4; c++) acc[a][b][c] = 0.f;

    const float4* hp = (const float4*)(g_hidden + erow * 64 + koff);
#pragma unroll
    for (int j = 0; j < 8; j++) {
        float4 v = hp[j];
        *(half2*)&sA[row * 72 + koff + j * 4]     = __floats2half2_rn(v.x, v.y);
        *(half2*)&sA[row * 72 + koff + j * 4 + 2] = __floats2half2_rn(v.z, v.w);
    }
    {
        const uint4* s = (const uint4*)(g_W2T + (n0 + row) * 64 + koff);
        uint4* d = (uint4*)&sB[row * 72 + koff];
        d[0] = s[0]; d[1] = s[1]; d[2] = s[2]; d[3] = s[3];
    }
    __syncthreads();
    tile_mma(sA, sB, wm, wn, lane, acc);

#pragma unroll
    for (int mt = 0; mt < 2; mt++)
#pragma unroll
        for (int nt = 0; nt < 8; nt++) {
            int er = m0 + wm + mt * 16 + g;
            int cn = n0 + wn + nt * 8 + tg * 2;
            float bb0 = b2[cn], bb1 = b2[cn + 1];
            if (er < M)
                *(half2*)&g_radial[er * 512 + cn] =
                    __floats2half2_rn(acc[mt][nt][0] + bb0, acc[mt][nt][1] + bb1);
            if (er + 8 < M)
                *(half2*)&g_radial[(er + 8) * 512 + cn] =
                    __floats2half2_rn(acc[mt][nt][2] + bb0, acc[mt][nt][3] + bb1);
        }
}

// ---------------- value = (z @ W_tp) * radial  (K=1024, register-built A) ----------------
__device__ __forceinline__ void load_B_wtp(half* sB, int n0, int row, int koff, int kc) {
    const half* src = g_WtpT + (n0 + row) * 1024 + kc * 64 + koff;
    half* dst = sB + row * 72 + koff;
#pragma unroll
    for (int j = 0; j < 4; j++) cp16(dst + j * 8, src + j * 8);
}

__global__ __launch_bounds__(256, 2) void k_value(const float* __restrict__ ein,
                                                  const float* __restrict__ esh, int M) {
    __shared__ half sB[2][128 * 72];
    int m0 = blockIdx.x * 128, n0 = blockIdx.y * 128;
    int tid = threadIdx.x, lane = tid & 31, wid = tid >> 5;
    int wm = (wid & 3) * 32, wn = (wid >> 2) * 64;
    int g = lane >> 2, tg = lane & 3;
    int row = tid >> 1, koff = (tid & 1) * 32;

    int b_r8 = ((lane >> 4) & 1) * 8;
    int b_k8 = lane & 8;
    int l7 = lane & 7;

    // A-fragment rows owned by this thread (2 m-tiles x 2 row-halves)
    int r[4];
    r[0] = min(m0 + wm + g,      M - 1);
    r[1] = min(m0 + wm + g + 8,  M - 1);
    r[2] = min(m0 + wm + g + 16, M - 1);
    r[3] = min(m0 + wm + g + 24, M - 1);

    // SH columns owned by this thread (fixed across all K): tg*2, tg*2+1, tg*2+8, tg*2+9
    float shf[4][4];
#pragma unroll
    for (int q = 0; q < 4; q++) {
        const float* sp = esh + r[q] * 16;
        shf[q][0] = __ldg(&sp[tg * 2]);
        shf[q][1] = __ldg(&sp[tg * 2 + 1]);
        shf[q][2] = __ldg(&sp[tg * 2 + 8]);
        shf[q][3] = __ldg(&sp[tg * 2 + 9]);
    }

    float acc[2][8][4];
#pragma unroll
    for (int a = 0; a < 2; a++)
#pragma unroll
        for (int b = 0; b < 8; b++)
#pragma unroll
            for (int c = 0; c < 4; c++) acc[a][b][c] = 0.f;

    // prologue: stage B chunk 0
    load_B_wtp(sB[0], n0, row, koff, 0);
    CP_COMMIT();
    CP_WAIT0();
    __syncthreads();

    for (int kc = 0; kc < 16; kc++) {
        int p = kc & 1;
        if (kc < 15) { load_B_wtp(sB[1 - p], n0, row, koff, kc + 1); CP_COMMIT(); }

        // ein for this chunk: cols kc*4 .. kc*4+3 for the 4 owned rows
        float4 ev[4];
#pragma unroll
        for (int q = 0; q < 4; q++)
            ev[q] = *(const float4*)(ein + r[q] * 64 + kc * 4);

        const half* sBp = sB[p];
#pragma unroll
        for (int ks = 0; ks < 4; ks++) {
            float e0 = ((const float*)&ev[0])[ks];
            float e1 = ((const float*)&ev[1])[ks];
            float e2 = ((const float*)&ev[2])[ks];
            float e3 = ((const float*)&ev[3])[ks];
            uint32_t af[2][4];
            af[0][0] = packh2(e0 * shf[0][0], e0 * shf[0][1]);
            af[0][1] = packh2(e1 * shf[1][0], e1 * shf[1][1]);
            af[0][2] = packh2(e0 * shf[0][2], e0 * shf[0][3]);
            af[0][3] = packh2(e1 * shf[1][2], e1 * shf[1][3]);
            af[1][0] = packh2(e2 * shf[2][0], e2 * shf[2][1]);
            af[1][1] = packh2(e3 * shf[3][0], e3 * shf[3][1]);
            af[1][2] = packh2(e2 * shf[2][2], e2 * shf[2][3]);
            af[1][3] = packh2(e3 * shf[3][2], e3 * shf[3][3]);

            uint32_t bf[4][4];
#pragma unroll
            for (int np = 0; np < 4; np++)
                ldsm4(bf[np], sBp + (wn + np * 16 + b_r8 + l7) * 72 + ks * 16 + b_k8);
#pragma unroll
            for (int np = 0; np < 4; np++) {
                mma_f16(acc[0][2 * np],     af[0], &bf[np][0]);
                mma_f16(acc[0][2 * np + 1], af[0], &bf[np][2]);
                mma_f16(acc[1][2 * np],     af[1], &bf[np][0]);
                mma_f16(acc[1][2 * np + 1], af[1], &bf[np][2]);
            }
        }
        if (kc < 15) {
            CP_WAIT0();
            __syncthreads();
        }
    }

    // epilogue: value = acc * radial (radial fp16, incl. bias)
#pragma unroll
    for (int mt = 0; mt < 2; mt++)
#pragma unroll
        for (int nt = 0; nt < 8; nt++) {
            int er = m0 + wm + mt * 16 + g;
            int cn = n0 + wn + nt * 8 + tg * 2;
            if (er < M) {
                float2 rr = __half22float2(*(const half2*)&g_radial[er * 512 + cn]);
                *(half2*)&g_value[er * 512 + cn] =
                    __floats2half2_rn(acc[mt][nt][0] * rr.x, acc[mt][nt][1] * rr.y);
            }
            if (er + 8 < M) {
                float2 rr = __half22float2(*(const half2*)&g_radial[(er + 8) * 512 + cn]);
                *(half2*)&g_value[(er + 8) * 512 + cn] =
                    __floats2half2_rn(acc[mt][nt][2] * rr.x, acc[mt][nt][3] * rr.y);
            }
        }
}

// ---------------- segment offsets (triple_idx0 sorted) ----------------
__global__ void k_seg(const int* __restrict__ t0, int E, int T) {
    int e = blockIdx.x * blockDim.x + threadIdx.x;
    if (e > E) return;
    int lo = 0, hi = T;
    while (lo < hi) {
        int mid = (lo + hi) >> 1;
        if (t0[mid] < e) lo = mid + 1; else hi = mid;
    }
    g_seg[e] = lo;
}

// ---------------- alpha MLPs (fp32, thread-per-triplet) ----------------
__global__ __launch_bounds__(128) void k_alpha(
    const float* __restrict__ emb2, const float* __restrict__ emb3,
    const float* __restrict__ aW1, const float* __restrict__ ab1,
    const float* __restrict__ ag1, const float* __restrict__ abe1,
    const float* __restrict__ aW2, const float* __restrict__ ab2,
    const float* __restrict__ ag2, const float* __restrict__ abe2,
    const float* __restrict__ aW3, const float* __restrict__ ab3, int T) {
    __shared__ float sW[64 * 64];
    __shared__ float sW3[64 * 8];
    __shared__ float sP[6 * 64];
    __shared__ float sb3[8];
    __shared__ float sx[64 * 129];
    int tid = threadIdx.x;
    int base = blockIdx.x * 128;
    int tri = base + tid;
    bool act = tri < T;
    float res[8];

    for (int br = 0; br < 2; br++) {
        const float* emb = br ? emb3 : emb2;
        __syncthreads();
        for (int li = tid; li < 128 * 64; li += 128) {
            int r = li >> 6, c = li & 63;
            int tt = min(base + r, T - 1);
            sx[c * 129 + r] = emb[tt * 64 + c];
        }
        for (int li = tid; li < 4096; li += 128) sW[li] = aW1[br * 4096 + li];
        for (int li = tid; li < 512; li += 128) sW3[li] = aW3[br * 512 + li];
        if (tid < 64) {
            sP[tid] = ab1[br * 64 + tid];        sP[64 + tid] = ag1[br * 64 + tid];
            sP[128 + tid] = abe1[br * 64 + tid]; sP[192 + tid] = ab2[br * 64 + tid];
            sP[256 + tid] = ag2[br * 64 + tid];  sP[320 + tid] = abe2[br * 64 + tid];
        }
        if (tid < 8) sb3[tid] = ab3[br * 8 + tid];
        __syncthreads();

        const float4* sW4 = (const float4*)sW;
        float h[64];
        // layer 1
#pragma unroll
        for (int j = 0; j < 64; j++) h[j] = sP[j];
        for (int i = 0; i < 64; i++) {
            float xv = sx[i * 129 + tid];
#pragma unroll
            for (int j4 = 0; j4 < 16; j4++) {
                float4 w = sW4[i * 16 + j4];
                h[4 * j4]     = fmaf(xv, w.x, h[4 * j4]);
                h[4 * j4 + 1] = fmaf(xv, w.y, h[4 * j4 + 1]);
                h[4 * j4 + 2] = fmaf(xv, w.z, h[4 * j4 + 2]);
                h[4 * j4 + 3] = fmaf(xv, w.w, h[4 * j4 + 3]);
            }
        }
        {
            float mu = 0.f;
#pragma unroll
            for (int j = 0; j < 64; j++) mu += h[j];
            mu *= (1.f / 64.f);
            float v = 0.f;
#pragma unroll
            for (int j = 0; j < 64; j++) { float d = h[j] - mu; v = fmaf(d, d, v); }
            float rr = rsqrtf(v * (1.f / 64.f) + 1e-6f);
#pragma unroll
            for (int j = 0; j < 64; j++) {
                float y = (h[j] - mu) * rr * sP[64 + j] + sP[128 + j];
                sx[j * 129 + tid] = y / (1.f + __expf(-y));
            }
        }
        __syncthreads();
        for (int li = tid; li < 4096; li += 128) sW[li] = aW2[br * 4096 + li];
        __syncthreads();
        // layer 2
#pragma unroll
        for (int j = 0; j < 64; j++) h[j] = sP[192 + j];
        for (int i = 0; i < 64; i++) {
            float xv = sx[i * 129 + tid];
#pragma unroll
            for (int j4 = 0; j4 < 16; j4++) {
                float4 w = sW4[i * 16 + j4];
                h[4 * j4]     = fmaf(xv, w.x, h[4 * j4]);
                h[4 * j4 + 1] = fmaf(xv, w.y, h[4 * j4 + 1]);
                h[4 * j4 + 2] = fmaf(xv, w.z, h[4 * j4 + 2]);
                h[4 * j4 + 3] = fmaf(xv, w.w, h[4 * j4 + 3]);
            }
        }
        {
            float mu = 0.f;
#pragma unroll
            for (int j = 0; j < 64; j++) mu += h[j];
            mu *= (1.f / 64.f);
            float v = 0.f;
#pragma unroll
            for (int j = 0; j < 64; j++) { float d = h[j] - mu; v = fmaf(d, d, v); }
            float rr = rsqrtf(v * (1.f / 64.f) + 1e-6f);
#pragma unroll
            for (int j = 0; j < 64; j++) {
                float y = (h[j] - mu) * rr * sP[256 + j] + sP[320 + j];
                sx[j * 129 + tid] = y / (1.f + __expf(-y));
            }
        }
        // layer 3 (reads own column only)
        const float4* sW34 = (const float4*)sW3;
        float o[8];
#pragma unroll
        for (int j = 0; j < 8; j++) o[j] = sb3[j];
        for (int i = 0; i < 64; i++) {
            float xv = sx[i * 129 + tid];
            float4 w0 = sW34[i * 2], w1 = sW34[i * 2 + 1];
            o[0] = fmaf(xv, w0.x, o[0]); o[1] = fmaf(xv, w0.y, o[1]);
            o[2] = fmaf(xv, w0.z, o[2]); o[3] = fmaf(xv, w0.w, o[3]);
            o[4] = fmaf(xv, w1.x, o[4]); o[5] = fmaf(xv, w1.y, o[5]);
            o[6] = fmaf(xv, w1.z, o[6]); o[7] = fmaf(xv, w1.w, o[7]);
        }
#pragma unroll
        for (int j = 0; j < 8; j++) res[j] = br ? res[j] * o[j] : o[j];
    }
    if (act) {
        float4* ap = (float4*)(g_alpha + tri * 8);
        ap[0] = make_float4(res[0], res[1], res[2], res[3]);
        ap[1] = make_float4(res[4], res[5], res[6], res[7]);
    }
}

// ---------------- segment softmax + gather-aggregate ----------------
__global__ void k_attn(const int* __restrict__ inv, const int* __restrict__ t1, int E) {
    int e = blockIdx.x * 8 + (threadIdx.x >> 5);
    if (e >= E) return;
    int lane = threadIdx.x & 31;
    int lo = g_seg[e], hi = g_seg[e + 1];
    int h = lane >> 2;
    float m = -1e30f;
    for (int t = lo; t < hi; t++) m = fmaxf(m, g_alpha[t * 8 + h]);
    float s = 0.f;
    for (int t = lo; t < hi; t++) s += __expf(g_alpha[t * 8 + h] - m);
    float inv_s = (s > 0.f) ? 1.f / s : 0.f;
    float acc[16];
#pragma unroll
    for (int j = 0; j < 16; j++) acc[j] = 0.f;
    for (int t = lo; t < hi; t++) {
        int es = inv[t1[t]];
        float w = __expf(g_alpha[t * 8 + h] - m) * inv_s;
        const uint4* vp = (const uint4*)(g_value + es * 512 + lane * 16);
        uint4 u0 = vp[0], u1 = vp[1];
        const half2* p0 = (const half2*)&u0;
        const half2* p1 = (const half2*)&u1;
#pragma unroll
        for (int j = 0; j < 4; j++) {
            float2 f0 = __half22float2(p0[j]);
            float2 f1 = __half22float2(p1[j]);
            acc[2 * j]         = fmaf(w, f0.x, acc[2 * j]);
            acc[2 * j + 1]     = fmaf(w, f0.y, acc[2 * j + 1]);
            acc[8 + 2 * j]     = fmaf(w, f1.x, acc[8 + 2 * j]);
            acc[8 + 2 * j + 1] = fmaf(w, f1.y, acc[8 + 2 * j + 1]);
        }
    }
    half2 o[8];
#pragma unroll
    for (int j = 0; j < 8; j++) o[j] = __floats2half2_rn(acc[2 * j], acc[2 * j + 1]);
    uint4* fp = (uint4*)(g_fea + e * 512 + lane * 16);
    fp[0] = *(uint4*)&o[0];
    fp[1] = *(uint4*)&o[4];
}

// ---------------- out = fea @ lin_W + lin_b  (pipelined) ----------------
__global__ __launch_bounds__(256, 2) void k_out(const float* __restrict__ linb,
                                                float* __restrict__ out, int M) {
    __shared__ half sA[2][128 * 72];
    __shared__ half sB[2][128 * 72];
    int m0 = blockIdx.x * 128;
    int tid = threadIdx.x, lane = tid & 31, wid = tid >> 5;
    int wm = (wid & 3) * 32, wn = (wid >> 2) * 64;
    int g = lane >> 2, tg = lane & 3;
    int row = tid >> 1, koff = (tid & 1) * 32;
    int erow = min(m0 + row, M - 1);

    float acc[2][8][4];
#pragma unroll
    for (int a = 0; a < 2; a++)
#pragma unroll
        for (int b = 0; b < 8; b++)
#pragma unroll
            for (int c = 0; c < 4; c++) acc[a][b][c] = 0.f;

    // prologue
    {
        const half* srcA = g_fea + erow * 512 + koff;
        const half* srcB = g_linWT + row * 512 + koff;
#pragma unroll
        for (int j = 0; j < 4; j++) {
            cp16(&sA[0][row * 72 + koff + j * 8], srcA + j * 8);
            cp16(&sB[0][row * 72 + koff + j * 8], srcB + j * 8);
        }
        CP_COMMIT(); CP_WAIT0();
        __syncthreads();
    }

    for (int kc = 0; kc < 8; kc++) {
        int p = kc & 1;
        if (kc < 7) {
            const half* srcA = g_fea + erow * 512 + (kc + 1) * 64 + koff;
            const half* srcB = g_linWT + row * 512 + (kc + 1) * 64 + koff;
#pragma unroll
            for (int j = 0; j < 4; j++) {
                cp16(&sA[1 - p][row * 72 + koff + j * 8], srcA + j * 8);
                cp16(&sB[1 - p][row * 72 + koff + j * 8], srcB + j * 8);
            }
            CP_COMMIT();
        }
        tile_mma(sA[p], sB[p], wm, wn, lane, acc);
        if (kc < 7) { CP_WAIT0(); __syncthreads(); }
    }
#pragma unroll
    for (int mt = 0; mt < 2; mt++)
#pragma unroll
        for (int nt = 0; nt < 8; nt++) {
            int er = m0 + wm + mt * 16 + g;
            int cn = wn + nt * 8 + tg * 2;
            float bb0 = linb[cn], bb1 = linb[cn + 1];
            if (er < M)
                *(float2*)&out[er * 128 + cn] =
                    make_float2(acc[mt][nt][0] + bb0, acc[mt][nt][1] + bb1);
            if (er + 8 < M)
                *(float2*)&out[(er + 8) * 128 + cn] =
                    make_float2(acc[mt][nt][2] + bb0, acc[mt][nt][3] + bb1);
        }
}

// ---------------- launcher ----------------
extern "C" void kernel_launch(void* const* d_in, const int* in_sizes, int n_in,
                              void* d_out, int out_size) {
    const float* edge_in = (const float*)d_in[0];
    const int*   inv     = (const int*)d_in[1];
    const float* esh     = (const float*)d_in[2];
    const float* elen    = (const float*)d_in[3];
    const int*   t0      = (const int*)d_in[6];
    const int*   t1      = (const int*)d_in[7];
    const float* emb2    = (const float*)d_in[8];
    const float* emb3    = (const float*)d_in[9];
    const float* Wtp     = (const float*)d_in[11];
    const float* rW1     = (const float*)d_in[12];
    const float* rb1     = (const float*)d_in[13];
    const float* rW2     = (const float*)d_in[14];
    const float* rb2     = (const float*)d_in[15];
    const float* aW1     = (const float*)d_in[16];
    const float* ab1     = (const float*)d_in[17];
    const float* ag1     = (const float*)d_in[18];
    const float* abe1    = (const float*)d_in[19];
    const float* aW2     = (const float*)d_in[20];
    const float* ab2     = (const float*)d_in[21];
    const float* ag2     = (const float*)d_in[22];
    const float* abe2    = (const float*)d_in[23];
    const float* aW3     = (const float*)d_in[24];
    const float* ab3     = (const float*)d_in[25];
    const float* linW    = (const float*)d_in[26];
    const float* linb    = (const float*)d_in[27];
    int E = in_sizes[0] / 64;
    int T = in_sizes[6];

    k_prep<<<512, 256>>>(Wtp, rW2, linW);
    k_hidden<<<CDIV(E, 4), 256>>>(elen, rW1, rb1, E);
    k_radial<<<dim3(CDIV(E, 128), 4), 256>>>(rb2, E);
    k_value<<<dim3(CDIV(E, 128), 4), 256>>>(edge_in, esh, E);
    k_seg<<<CDIV(E + 1, 256), 256>>>(t0, E, T);
    k_alpha<<<CDIV(T, 128), 128>>>(emb2, emb3, aW1, ab1, ag1, abe1,
                                   aW2, ab2, ag2, abe2, aW3, ab3, T);
    k_attn<<<CDIV(E, 8), 256>>>(inv, t1, E);
    k_out<<<CDIV(E, 128), 256>>>(linb, (float*)d_out, E);
}

// round 7
// speedup vs baseline: 1.1983x; 1.0100x over previous
#include <cuda_runtime.h>
#include <cuda_fp16.h>
#include <cstdint>

#define CDIV(a,b) (((a)+(b)-1)/(b))

// ---------------- static device scratch ----------------
__device__ __align__(16) half  g_WtpT  [512 * 1024];
__device__ __align__(16) half  g_W2T   [512 * 64];
__device__ __align__(16) half  g_linWT [128 * 512];
__device__ __align__(16) float g_hidden[160000 * 64];
__device__ __align__(16) half  g_radial[160000 * 512];
__device__ __align__(16) half  g_value [160000 * 512];
__device__ __align__(16) float g_alpha [250000 * 8];
__device__              int    g_seg   [160001];
__device__ __align__(16) half  g_fea   [160000 * 512];

// ---------------- PTX helpers ----------------
__device__ __forceinline__ void mma_f16(float* c, const uint32_t* a, const uint32_t* b) {
    asm volatile(
        "mma.sync.aligned.m16n8k16.row.col.f32.f16.f16.f32 "
        "{%0,%1,%2,%3},{%4,%5,%6,%7},{%8,%9},{%0,%1,%2,%3};\n"
        : "+f"(c[0]), "+f"(c[1]), "+f"(c[2]), "+f"(c[3])
        : "r"(a[0]), "r"(a[1]), "r"(a[2]), "r"(a[3]), "r"(b[0]), "r"(b[1]));
}

__device__ __forceinline__ void ldsm4(uint32_t* d, const half* p) {
    uint32_t a = (uint32_t)__cvta_generic_to_shared(p);
    asm volatile("ldmatrix.sync.aligned.m8n8.x4.shared.b16 {%0,%1,%2,%3},[%4];\n"
        : "=r"(d[0]), "=r"(d[1]), "=r"(d[2]), "=r"(d[3]) : "r"(a));
}

__device__ __forceinline__ void cp16(void* smem, const void* gmem) {
    uint32_t s = (uint32_t)__cvta_generic_to_shared(smem);
    asm volatile("cp.async.cg.shared.global [%0], [%1], 16;\n" :: "r"(s), "l"(gmem));
}
#define CP_COMMIT() asm volatile("cp.async.commit_group;\n")
#define CP_WAIT0()  asm volatile("cp.async.wait_group 0;\n")
#define CP_WAIT1()  asm volatile("cp.async.wait_group 1;\n")

__device__ __forceinline__ uint32_t packh2(float a, float b) {
    half2 h = __floats2half2_rn(a, b);
    return *(uint32_t*)&h;
}

// one 64-deep K-chunk of mma on 128x128 tile; warp covers 32(m)x64(n).
// smem row stride = 72 halfs (144B): ldmatrix row addrs hit 32 distinct banks.
__device__ __forceinline__ void tile_mma(const half* sA, const half* sB,
                                         int wm, int wn, int lane,
                                         float acc[2][8][4]) {
    int r15 = lane & 15;
    int a_k8 = ((lane >> 4) & 1) * 8;
    int b_r8 = ((lane >> 4) & 1) * 8;
    int b_k8 = lane & 8;
    int l7 = lane & 7;
#pragma unroll
    for (int ks = 0; ks < 4; ks++) {
        uint32_t af[2][4];
#pragma unroll
        for (int mt = 0; mt < 2; mt++)
            ldsm4(af[mt], sA + (wm + mt * 16 + r15) * 72 + ks * 16 + a_k8);
        uint32_t bf[4][4];
#pragma unroll
        for (int np = 0; np < 4; np++)
            ldsm4(bf[np], sB + (wn + np * 16 + b_r8 + l7) * 72 + ks * 16 + b_k8);
#pragma unroll
        for (int np = 0; np < 4; np++) {
            mma_f16(acc[0][2 * np],     af[0], &bf[np][0]);
            mma_f16(acc[0][2 * np + 1], af[0], &bf[np][2]);
            mma_f16(acc[1][2 * np],     af[1], &bf[np][0]);
            mma_f16(acc[1][2 * np + 1], af[1], &bf[np][2]);
        }
    }
}

// ---------------- weight prep ----------------
__global__ void k_prep(const float* __restrict__ Wtp, const float* __restrict__ W2,
                       const float* __restrict__ linW) {
    int i = blockIdx.x * blockDim.x + threadIdx.x;
    int stride = gridDim.x * blockDim.x;
    for (int idx = i; idx < 512 * 1024; idx += stride) {
        int n = idx >> 10, k = idx & 1023;
        g_WtpT[idx] = __float2half_rn(Wtp[k * 512 + n]);
    }
    for (int idx = i; idx < 512 * 64; idx += stride) {
        int n = idx >> 6, k = idx & 63;
        g_W2T[idx] = __float2half_rn(W2[k * 512 + n]);
    }
    for (int idx = i; idx < 128 * 512; idx += stride) {
        int n = idx >> 9, k = idx & 511;
        g_linWT[idx] = __float2half_rn(linW[k * 128 + n]);
    }
}

// ---------------- hidden = silu(emb @ W1 + b1) ----------------
__global__ void k_hidden(const float* __restrict__ emb, const float* __restrict__ W1,
                         const float* __restrict__ b1, int E) {
    __shared__ float s_e[4][64];
    int tid = threadIdx.x;
    int slot = tid >> 6, j = tid & 63;
    int e = blockIdx.x * 4 + slot;
    int ec = min(e, E - 1);
    s_e[slot][j] = emb[ec * 64 + j];
    __syncthreads();
    float acc = b1[j];
#pragma unroll 8
    for (int i = 0; i < 64; i++) acc = fmaf(s_e[slot][i], W1[i * 64 + j], acc);
    float y = acc / (1.f + __expf(-acc));
    if (e < E) g_hidden[e * 64 + j] = y;
}

// ---------------- radial = hidden @ W2 + b2  (K=64 mma) ----------------
__global__ __launch_bounds__(256) void k_radial(const float* __restrict__ b2, int M) {
    __shared__ half sA[128 * 72];
    __shared__ half sB[128 * 72];
    int m0 = blockIdx.x * 128, n0 = blockIdx.y * 128;
    int tid = threadIdx.x, lane = tid & 31, wid = tid >> 5;
    int wm = (wid & 3) * 32, wn = (wid >> 2) * 64;
    int g = lane >> 2, tg = lane & 3;
    int row = tid >> 1, koff = (tid & 1) * 32;
    int erow = min(m0 + row, M - 1);

    float acc[2][8][4];
#pragma unroll
    for (int a = 0; a < 2; a++)
#pragma unroll
        for (int b = 0; b < 8; b++)
#pragma unroll
            for (int c = 0; c < 4; c++) acc[a][b][c] = 0.f;

    const float4* hp = (const float4*)(g_hidden + erow * 64 + koff);
#pragma unroll
    for (int j = 0; j < 8; j++) {
        float4 v = hp[j];
        *(half2*)&sA[row * 72 + koff + j * 4]     = __floats2half2_rn(v.x, v.y);
        *(half2*)&sA[row * 72 + koff + j * 4 + 2] = __floats2half2_rn(v.z, v.w);
    }
    {
        const uint4* s = (const uint4*)(g_W2T + (n0 + row) * 64 + koff);
        uint4* d = (uint4*)&sB[row * 72 + koff];
        d[0] = s[0]; d[1] = s[1]; d[2] = s[2]; d[3] = s[3];
    }
    __syncthreads();
    tile_mma(sA, sB, wm, wn, lane, acc);

#pragma unroll
    for (int mt = 0; mt < 2; mt++)
#pragma unroll
        for (int nt = 0; nt < 8; nt++) {
            int er = m0 + wm + mt * 16 + g;
            int cn = n0 + wn + nt * 8 + tg * 2;
            float bb0 = b2[cn], bb1 = b2[cn + 1];
            if (er < M)
                *(half2*)&g_radial[er * 512 + cn] =
                    __floats2half2_rn(acc[mt][nt][0] + bb0, acc[mt][nt][1] + bb1);
            if (er + 8 < M)
                *(half2*)&g_radial[(er + 8) * 512 + cn] =
                    __floats2half2_rn(acc[mt][nt][2] + bb0, acc[mt][nt][3] + bb1);
        }
}

// ---------------- value = (z @ W_tp) * radial ----------------
// K=1024, register-built A, 3-stage cp.async ring (B tile + ein slice per stage)
__global__ __launch_bounds__(256, 2) void k_value(const float* __restrict__ ein,
                                                  const float* __restrict__ esh, int M) {
    __shared__ half  sB[3][128 * 72];
    __shared__ float sE[3][128 * 4];
    int m0 = blockIdx.x * 128, n0 = blockIdx.y * 128;
    int tid = threadIdx.x, lane = tid & 31, wid = tid >> 5;
    int wm = (wid & 3) * 32, wn = (wid >> 2) * 64;
    int g = lane >> 2, tg = lane & 3;
    int row = tid >> 1, koff = (tid & 1) * 32;

    int b_r8 = ((lane >> 4) & 1) * 8;
    int b_k8 = lane & 8;
    int l7 = lane & 7;

    // local + clamped-global A-fragment rows (2 m-tiles x 2 row-halves)
    int lr[4], r[4];
#pragma unroll
    for (int q = 0; q < 4; q++) {
        lr[q] = wm + g + ((q & 1) ? 8 : 0) + ((q >> 1) ? 16 : 0);
        r[q]  = min(m0 + lr[q], M - 1);
    }

    // SH columns owned by this thread (fixed across all K)
    float shf[4][4];
#pragma unroll
    for (int q = 0; q < 4; q++) {
        const float* sp = esh + r[q] * 16;
        shf[q][0] = __ldg(&sp[tg * 2]);
        shf[q][1] = __ldg(&sp[tg * 2 + 1]);
        shf[q][2] = __ldg(&sp[tg * 2 + 8]);
        shf[q][3] = __ldg(&sp[tg * 2 + 9]);
    }

    // stage loaders
    int e_row = min(m0 + (tid & 127), M - 1);   // threads 0..127 load ein rows
    auto load_stage = [&](int s, int kc) {
        const half* src = g_WtpT + (n0 + row) * 1024 + kc * 64 + koff;
        half* dst = &sB[s][row * 72 + koff];
#pragma unroll
        for (int j = 0; j < 4; j++) cp16(dst + j * 8, src + j * 8);
        if (tid < 128)
            cp16(&sE[s][tid * 4], ein + e_row * 64 + kc * 4);
    };

    float acc[2][8][4];
#pragma unroll
    for (int a = 0; a < 2; a++)
#pragma unroll
        for (int b = 0; b < 8; b++)
#pragma unroll
            for (int c = 0; c < 4; c++) acc[a][b][c] = 0.f;

    // prologue: stage chunks 0 and 1
    load_stage(0, 0); CP_COMMIT();
    load_stage(1, 1); CP_COMMIT();
    CP_WAIT1();               // stage 0 complete
    __syncthreads();

    for (int kc = 0; kc < 16; kc++) {
        int p = kc % 3;
        if (kc < 14) { load_stage((kc + 2) % 3, kc + 2); CP_COMMIT(); }

        // ein values for this chunk from smem (broadcast LDS.128)
        float4 ev[4];
#pragma unroll
        for (int q = 0; q < 4; q++)
            ev[q] = *(const float4*)&sE[p][lr[q] * 4];

        const half* sBp = sB[p];
#pragma unroll
        for (int ks = 0; ks < 4; ks++) {
            float e0 = ((const float*)&ev[0])[ks];
            float e1 = ((const float*)&ev[1])[ks];
            float e2 = ((const float*)&ev[2])[ks];
            float e3 = ((const float*)&ev[3])[ks];
            uint32_t af[2][4];
            af[0][0] = packh2(e0 * shf[0][0], e0 * shf[0][1]);
            af[0][1] = packh2(e1 * shf[1][0], e1 * shf[1][1]);
            af[0][2] = packh2(e0 * shf[0][2], e0 * shf[0][3]);
            af[0][3] = packh2(e1 * shf[1][2], e1 * shf[1][3]);
            af[1][0] = packh2(e2 * shf[2][0], e2 * shf[2][1]);
            af[1][1] = packh2(e3 * shf[3][0], e3 * shf[3][1]);
            af[1][2] = packh2(e2 * shf[2][2], e2 * shf[2][3]);
            af[1][3] = packh2(e3 * shf[3][2], e3 * shf[3][3]);

            uint32_t bf[4][4];
#pragma unroll
            for (int np = 0; np < 4; np++)
                ldsm4(bf[np], sBp + (wn + np * 16 + b_r8 + l7) * 72 + ks * 16 + b_k8);
#pragma unroll
            for (int np = 0; np < 4; np++) {
                mma_f16(acc[0][2 * np],     af[0], &bf[np][0]);
                mma_f16(acc[0][2 * np + 1], af[0], &bf[np][2]);
                mma_f16(acc[1][2 * np],     af[1], &bf[np][0]);
                mma_f16(acc[1][2 * np + 1], af[1], &bf[np][2]);
            }
        }
        if (kc < 15) {
            CP_WAIT1();       // next stage complete (lookahead stage may still fly)
            __syncthreads();
        }
    }

    // epilogue: value = acc * radial (radial fp16, incl. bias)
#pragma unroll
    for (int mt = 0; mt < 2; mt++)
#pragma unroll
        for (int nt = 0; nt < 8; nt++) {
            int er = m0 + wm + mt * 16 + g;
            int cn = n0 + wn + nt * 8 + tg * 2;
            if (er < M) {
                float2 rr = __half22float2(*(const half2*)&g_radial[er * 512 + cn]);
                *(half2*)&g_value[er * 512 + cn] =
                    __floats2half2_rn(acc[mt][nt][0] * rr.x, acc[mt][nt][1] * rr.y);
            }
            if (er + 8 < M) {
                float2 rr = __half22float2(*(const half2*)&g_radial[(er + 8) * 512 + cn]);
                *(half2*)&g_value[(er + 8) * 512 + cn] =
                    __floats2half2_rn(acc[mt][nt][2] * rr.x, acc[mt][nt][3] * rr.y);
            }
        }
}

// ---------------- segment offsets (triple_idx0 sorted) ----------------
__global__ void k_seg(const int* __restrict__ t0, int E, int T) {
    int e = blockIdx.x * blockDim.x + threadIdx.x;
    if (e > E) return;
    int lo = 0, hi = T;
    while (lo < hi) {
        int mid = (lo + hi) >> 1;
        if (t0[mid] < e) lo = mid + 1; else hi = mid;
    }
    g_seg[e] = lo;
}

// ---------------- alpha MLPs (fp32, thread-per-triplet) ----------------
__global__ __launch_bounds__(128) void k_alpha(
    const float* __restrict__ emb2, const float* __restrict__ emb3,
    const float* __restrict__ aW1, const float* __restrict__ ab1,
    const float* __restrict__ ag1, const float* __restrict__ abe1,
    const float* __restrict__ aW2, const float* __restrict__ ab2,
    const float* __restrict__ ag2, const float* __restrict__ abe2,
    const float* __restrict__ aW3, const float* __restrict__ ab3, int T) {
    __shared__ float sW[64 * 64];
    __shared__ float sW3[64 * 8];
    __shared__ float sP[6 * 64];
    __shared__ float sb3[8];
    __shared__ float sx[64 * 129];
    int tid = threadIdx.x;
    int base = blockIdx.x * 128;
    int tri = base + tid;
    bool act = tri < T;
    float res[8];

    for (int br = 0; br < 2; br++) {
        const float* emb = br ? emb3 : emb2;
        __syncthreads();
        for (int li = tid; li < 128 * 64; li += 128) {
            int r = li >> 6, c = li & 63;
            int tt = min(base + r, T - 1);
            sx[c * 129 + r] = emb[tt * 64 + c];
        }
        for (int li = tid; li < 4096; li += 128) sW[li] = aW1[br * 4096 + li];
        for (int li = tid; li < 512; li += 128) sW3[li] = aW3[br * 512 + li];
        if (tid < 64) {
            sP[tid] = ab1[br * 64 + tid];        sP[64 + tid] = ag1[br * 64 + tid];
            sP[128 + tid] = abe1[br * 64 + tid]; sP[192 + tid] = ab2[br * 64 + tid];
            sP[256 + tid] = ag2[br * 64 + tid];  sP[320 + tid] = abe2[br * 64 + tid];
        }
        if (tid < 8) sb3[tid] = ab3[br * 8 + tid];
        __syncthreads();

        const float4* sW4 = (const float4*)sW;
        float h[64];
        // layer 1
#pragma unroll
        for (int j = 0; j < 64; j++) h[j] = sP[j];
        for (int i = 0; i < 64; i++) {
            float xv = sx[i * 129 + tid];
#pragma unroll
            for (int j4 = 0; j4 < 16; j4++) {
                float4 w = sW4[i * 16 + j4];
                h[4 * j4]     = fmaf(xv, w.x, h[4 * j4]);
                h[4 * j4 + 1] = fmaf(xv, w.y, h[4 * j4 + 1]);
                h[4 * j4 + 2] = fmaf(xv, w.z, h[4 * j4 + 2]);
                h[4 * j4 + 3] = fmaf(xv, w.w, h[4 * j4 + 3]);
            }
        }
        {
            float mu = 0.f;
#pragma unroll
            for (int j = 0; j < 64; j++) mu += h[j];
            mu *= (1.f / 64.f);
            float v = 0.f;
#pragma unroll
            for (int j = 0; j < 64; j++) { float d = h[j] - mu; v = fmaf(d, d, v); }
            float rr = rsqrtf(v * (1.f / 64.f) + 1e-6f);
#pragma unroll
            for (int j = 0; j < 64; j++) {
                float y = (h[j] - mu) * rr * sP[64 + j] + sP[128 + j];
                sx[j * 129 + tid] = y / (1.f + __expf(-y));
            }
        }
        __syncthreads();
        for (int li = tid; li < 4096; li += 128) sW[li] = aW2[br * 4096 + li];
        __syncthreads();
        // layer 2
#pragma unroll
        for (int j = 0; j < 64; j++) h[j] = sP[192 + j];
        for (int i = 0; i < 64; i++) {
            float xv = sx[i * 129 + tid];
#pragma unroll
            for (int j4 = 0; j4 < 16; j4++) {
                float4 w = sW4[i * 16 + j4];
                h[4 * j4]     = fmaf(xv, w.x, h[4 * j4]);
                h[4 * j4 + 1] = fmaf(xv, w.y, h[4 * j4 + 1]);
                h[4 * j4 + 2] = fmaf(xv, w.z, h[4 * j4 + 2]);
                h[4 * j4 + 3] = fmaf(xv, w.w, h[4 * j4 + 3]);
            }
        }
        {
            float mu = 0.f;
#pragma unroll
            for (int j = 0; j < 64; j++) mu += h[j];
            mu *= (1.f / 64.f);
            float v = 0.f;
#pragma unroll
            for (int j = 0; j < 64; j++) { float d = h[j] - mu; v = fmaf(d, d, v); }
            float rr = rsqrtf(v * (1.f / 64.f) + 1e-6f);
#pragma unroll
            for (int j = 0; j < 64; j++) {
                float y = (h[j] - mu) * rr * sP[256 + j] + sP[320 + j];
                sx[j * 129 + tid] = y / (1.f + __expf(-y));
            }
        }
        // layer 3 (reads own column only)
        const float4* sW34 = (const float4*)sW3;
        float o[8];
#pragma unroll
        for (int j = 0; j < 8; j++) o[j] = sb3[j];
        for (int i = 0; i < 64; i++) {
            float xv = sx[i * 129 + tid];
            float4 w0 = sW34[i * 2], w1 = sW34[i * 2 + 1];
            o[0] = fmaf(xv, w0.x, o[0]); o[1] = fmaf(xv, w0.y, o[1]);
            o[2] = fmaf(xv, w0.z, o[2]); o[3] = fmaf(xv, w0.w, o[3]);
            o[4] = fmaf(xv, w1.x, o[4]); o[5] = fmaf(xv, w1.y, o[5]);
            o[6] = fmaf(xv, w1.z, o[6]); o[7] = fmaf(xv, w1.w, o[7]);
        }
#pragma unroll
        for (int j = 0; j < 8; j++) res[j] = br ? res[j] * o[j] : o[j];
    }
    if (act) {
        float4* ap = (float4*)(g_alpha + tri * 8);
        ap[0] = make_float4(res[0], res[1], res[2], res[3]);
        ap[1] = make_float4(res[4], res[5], res[6], res[7]);
    }
}

// ---------------- segment softmax + gather-aggregate ----------------
__global__ void k_attn(const int* __restrict__ inv, const int* __restrict__ t1, int E) {
    int e = blockIdx.x * 8 + (threadIdx.x >> 5);
    if (e >= E) return;
    int lane = threadIdx.x & 31;
    int lo = g_seg[e], hi = g_seg[e + 1];
    int h = lane >> 2;
    float m = -1e30f;
    for (int t = lo; t < hi; t++) m = fmaxf(m, g_alpha[t * 8 + h]);
    float s = 0.f;
    for (int t = lo; t < hi; t++) s += __expf(g_alpha[t * 8 + h] - m);
    float inv_s = (s > 0.f) ? 1.f / s : 0.f;
    float acc[16];
#pragma unroll
    for (int j = 0; j < 16; j++) acc[j] = 0.f;
    for (int t = lo; t < hi; t++) {
        int es = inv[t1[t]];
        float w = __expf(g_alpha[t * 8 + h] - m) * inv_s;
        const uint4* vp = (const uint4*)(g_value + es * 512 + lane * 16);
        uint4 u0 = vp[0], u1 = vp[1];
        const half2* p0 = (const half2*)&u0;
        const half2* p1 = (const half2*)&u1;
#pragma unroll
        for (int j = 0; j < 4; j++) {
            float2 f0 = __half22float2(p0[j]);
            float2 f1 = __half22float2(p1[j]);
            acc[2 * j]         = fmaf(w, f0.x, acc[2 * j]);
            acc[2 * j + 1]     = fmaf(w, f0.y, acc[2 * j + 1]);
            acc[8 + 2 * j]     = fmaf(w, f1.x, acc[8 + 2 * j]);
            acc[8 + 2 * j + 1] = fmaf(w, f1.y, acc[8 + 2 * j + 1]);
        }
    }
    half2 o[8];
#pragma unroll
    for (int j = 0; j < 8; j++) o[j] = __floats2half2_rn(acc[2 * j], acc[2 * j + 1]);
    uint4* fp = (uint4*)(g_fea + e * 512 + lane * 16);
    fp[0] = *(uint4*)&o[0];
    fp[1] = *(uint4*)&o[4];
}

// ---------------- out = fea @ lin_W + lin_b  (pipelined) ----------------
__global__ __launch_bounds__(256, 2) void k_out(const float* __restrict__ linb,
                                                float* __restrict__ out, int M) {
    __shared__ half sA[2][128 * 72];
    __shared__ half sB[2][128 * 72];
    int m0 = blockIdx.x * 128;
    int tid = threadIdx.x, lane = tid & 31, wid = tid >> 5;
    int wm = (wid & 3) * 32, wn = (wid >> 2) * 64;
    int g = lane >> 2, tg = lane & 3;
    int row = tid >> 1, koff = (tid & 1) * 32;
    int erow = min(m0 + row, M - 1);

    float acc[2][8][4];
#pragma unroll
    for (int a = 0; a < 2; a++)
#pragma unroll
        for (int b = 0; b < 8; b++)
#pragma unroll
            for (int c = 0; c < 4; c++) acc[a][b][c] = 0.f;

    // prologue
    {
        const half* srcA = g_fea + erow * 512 + koff;
        const half* srcB = g_linWT + row * 512 + koff;
#pragma unroll
        for (int j = 0; j < 4; j++) {
            cp16(&sA[0][row * 72 + koff + j * 8], srcA + j * 8);
            cp16(&sB[0][row * 72 + koff + j * 8], srcB + j * 8);
        }
        CP_COMMIT(); CP_WAIT0();
        __syncthreads();
    }

    for (int kc = 0; kc < 8; kc++) {
        int p = kc & 1;
        if (kc < 7) {
            const half* srcA = g_fea + erow * 512 + (kc + 1) * 64 + koff;
            const half* srcB = g_linWT + row * 512 + (kc + 1) * 64 + koff;
#pragma unroll
            for (int j = 0; j < 4; j++) {
                cp16(&sA[1 - p][row * 72 + koff + j * 8], srcA + j * 8);
                cp16(&sB[1 - p][row * 72 + koff + j * 8], srcB + j * 8);
            }
            CP_COMMIT();
        }
        tile_mma(sA[p], sB[p], wm, wn, lane, acc);
        if (kc < 7) { CP_WAIT0(); __syncthreads(); }
    }
#pragma unroll
    for (int mt = 0; mt < 2; mt++)
#pragma unroll
        for (int nt = 0; nt < 8; nt++) {
            int er = m0 + wm + mt * 16 + g;
            int cn = wn + nt * 8 + tg * 2;
            float bb0 = linb[cn], bb1 = linb[cn + 1];
            if (er < M)
                *(float2*)&out[er * 128 + cn] =
                    make_float2(acc[mt][nt][0] + bb0, acc[mt][nt][1] + bb1);
            if (er + 8 < M)
                *(float2*)&out[(er + 8) * 128 + cn] =
                    make_float2(acc[mt][nt][2] + bb0, acc[mt][nt][3] + bb1);
        }
}

// ---------------- launcher ----------------
extern "C" void kernel_launch(void* const* d_in, const int* in_sizes, int n_in,
                              void* d_out, int out_size) {
    const float* edge_in = (const float*)d_in[0];
    const int*   inv     = (const int*)d_in[1];
    const float* esh     = (const float*)d_in[2];
    const float* elen    = (const float*)d_in[3];
    const int*   t0      = (const int*)d_in[6];
    const int*   t1      = (const int*)d_in[7];
    const float* emb2    = (const float*)d_in[8];
    const float* emb3    = (const float*)d_in[9];
    const float* Wtp     = (const float*)d_in[11];
    const float* rW1     = (const float*)d_in[12];
    const float* rb1     = (const float*)d_in[13];
    const float* rW2     = (const float*)d_in[14];
    const float* rb2     = (const float*)d_in[15];
    const float* aW1     = (const float*)d_in[16];
    const float* ab1     = (const float*)d_in[17];
    const float* ag1     = (const float*)d_in[18];
    const float* abe1    = (const float*)d_in[19];
    const float* aW2     = (const float*)d_in[20];
    const float* ab2     = (const float*)d_in[21];
    const float* ag2     = (const float*)d_in[22];
    const float* abe2    = (const float*)d_in[23];
    const float* aW3     = (const float*)d_in[24];
    const float* ab3     = (const float*)d_in[25];
    const float* linW    = (const float*)d_in[26];
    const float* linb    = (const float*)d_in[27];
    int E = in_sizes[0] / 64;
    int T = in_sizes[6];

    k_prep<<<512, 256>>>(Wtp, rW2, linW);
    k_hidden<<<CDIV(E, 4), 256>>>(elen, rW1, rb1, E);
    k_radial<<<dim3(CDIV(E, 128), 4), 256>>>(rb2, E);
    k_value<<<dim3(CDIV(E, 128), 4), 256>>>(edge_in, esh, E);
    k_seg<<<CDIV(E + 1, 256), 256>>>(t0, E, T);
    k_alpha<<<CDIV(T, 128), 128>>>(emb2, emb3, aW1, ab1, ag1, abe1,
                                   aW2, ab2, ag2, abe2, aW3, ab3, T);
    k_attn<<<CDIV(E, 8), 256>>>(inv, t1, E);
    k_out<<<CDIV(E, 128), 256>>>(linb, (float*)d_out, E);
}